// round 3
// baseline (speedup 1.0000x reference)
#include <cuda_runtime.h>

// =============================================================================
// FFT convolution: out = irfft( rfft(x, 2L) * rfft(squash(smooth(kern)), 2L) )[:L]
// L = 8192, N = 2L = 16384 real FFT == M = 8192 complex FFT on even/odd packing.
// Complex FFT: Stockham, 3 radix-16 register-resident stages + 1 radix-2 stage,
// bank-conflict-free padded smem (PAD), 139 KB ping-pong, one block per row.
// =============================================================================

#define L_SIG    8192
#define M_FFT    8192      // complex FFT size (= N/2)
#define MH       4096      // M/2
#define NCH      256
#define NROWS    2048      // 8 * 256
#define NTHREADS 512
#define KERN_LAM 0.003f

#define PAD(i)   ((i) + ((i) >> 4))      // conflict-free smem addressing
#define SBUF     8704                     // PAD(8191)+2 rounded: 8192 + 512

// Kernel spectrum: 256 rows x 8193 complex bins (rfft of length-16384 signal)
__device__ float2 g_kf[NCH * (2 * MH + 1)];
// Twiddle tables (filled each launch by twiddle_init; deterministic)
__device__ float2 g_tw [M_FFT];   // exp(-2*pi*i * r / M)  (only r<512 used by FFT)
__device__ float2 g_tw2[MH + 1];  // exp(-pi*i  * k / M),  k in [0, 4096]

__device__ __forceinline__ float2 cmul(float2 a, float2 b) {
    return make_float2(fmaf(a.x, b.x, -a.y * b.y), fmaf(a.x, b.y, a.y * b.x));
}

__global__ void twiddle_init() {
    int i = blockIdx.x * blockDim.x + threadIdx.x;
    if (i < M_FFT) {
        double s, c;
        sincospi(-2.0 * (double)i / (double)M_FFT, &s, &c);
        g_tw[i] = make_float2((float)c, (float)s);
    }
    if (i <= MH) {
        double s, c;
        sincospi(-1.0 * (double)i / (double)M_FFT, &s, &c);
        g_tw2[i] = make_float2((float)c, (float)s);
    }
}

// ---------------------------------------------------------------------------
// 4-point DFT (forward): o0..o3 = DFT4(a,b,c,d), W4 = -i.
// ---------------------------------------------------------------------------
__device__ __forceinline__ void dft4(float2 a, float2 b, float2 c, float2 d,
                                     float2& o0, float2& o1, float2& o2, float2& o3) {
    float2 apc = make_float2(a.x + c.x, a.y + c.y);
    float2 amc = make_float2(a.x - c.x, a.y - c.y);
    float2 bpd = make_float2(b.x + d.x, b.y + d.y);
    float2 bmd = make_float2(b.x - d.x, b.y - d.y);
    o0 = make_float2(apc.x + bpd.x, apc.y + bpd.y);
    o1 = make_float2(amc.x + bmd.y, amc.y - bmd.x);   // amc - i*bmd
    o2 = make_float2(apc.x - bpd.x, apc.y - bpd.y);
    o3 = make_float2(amc.x - bmd.y, amc.y + bmd.x);   // amc + i*bmd
}

// ---------------------------------------------------------------------------
// In-register 16-point forward DFT (v[j] <- X_j). Two radix-4 layers with
// W16 twiddles: X[k1+4k2] = DFT4_{n1,k2}( W16^{n1*k1} * DFT4_{n2,k1}(x[n1+4n2]) )
// ---------------------------------------------------------------------------
__device__ __forceinline__ void dft16(float2* v) {
    const float2 W1 = make_float2( 0.9238795325112867f, -0.3826834323650898f);
    const float2 W2 = make_float2( 0.7071067811865476f, -0.7071067811865476f);
    const float2 W3 = make_float2( 0.3826834323650898f, -0.9238795325112867f);
    const float2 W6 = make_float2(-0.7071067811865476f, -0.7071067811865476f);
    const float2 W9 = make_float2(-0.9238795325112867f,  0.3826834323650898f);
    float2 A[4][4];
    #pragma unroll
    for (int n1 = 0; n1 < 4; n1++)
        dft4(v[n1], v[n1 + 4], v[n1 + 8], v[n1 + 12],
             A[n1][0], A[n1][1], A[n1][2], A[n1][3]);
    A[1][1] = cmul(A[1][1], W1);
    A[1][2] = cmul(A[1][2], W2);
    A[1][3] = cmul(A[1][3], W3);
    A[2][1] = cmul(A[2][1], W2);
    A[2][2] = make_float2(A[2][2].y, -A[2][2].x);     // * W16^4 = -i
    A[2][3] = cmul(A[2][3], W6);
    A[3][1] = cmul(A[3][1], W3);
    A[3][2] = cmul(A[3][2], W6);
    A[3][3] = cmul(A[3][3], W9);
    #pragma unroll
    for (int k1 = 0; k1 < 4; k1++)
        dft4(A[0][k1], A[1][k1], A[2][k1], A[3][k1],
             v[k1], v[k1 + 4], v[k1 + 8], v[k1 + 12]);
}

// ---------------------------------------------------------------------------
// Stockham autosort FFT of size M=8192: 3 radix-16 stages (s = 1, 16, 256)
// + 1 final radix-2 stage (s = 4096, twiddle = 1). 512 threads, one radix-16
// butterfly per thread per stage. Ping-pong x<->y; returns result buffer.
// All smem indices go through PAD (conflict-free, verified per stage).
// Caller must have __syncthreads()'d after writing the input buffer.
// ---------------------------------------------------------------------------
__device__ float2* fft_m(float2* x, float2* y) {
    const int tid = threadIdx.x;
    int s = 1;
    #pragma unroll
    for (int st = 0; st < 3; st++) {
        const int q = tid & (s - 1);
        const int r = tid - q;                 // = p * s  (< 512 always)
        float2 v[16];
        #pragma unroll
        for (int i = 0; i < 16; i++) v[i] = x[PAD(tid + i * NTHREADS)];
        dft16(v);
        const int o = 16 * tid - 15 * q;
        y[PAD(o)] = v[0];
        float2 w1 = g_tw[r];
        float2 wj = w1;
        #pragma unroll
        for (int j = 1; j < 16; j++) {         // y[o+j*s] = W_M^{j*r} * X_j
            y[PAD(o + j * s)] = cmul(v[j], wj);
            wj = cmul(wj, w1);
        }
        __syncthreads();
        float2* tmp = x; x = y; y = tmp;
        s <<= 4;
    }
    // final radix-2 stage: s = 4096 -> q = t, o = t, twiddle = W^0 = 1
    #pragma unroll
    for (int i = 0; i < (MH / NTHREADS); i++) {
        int t = tid + i * NTHREADS;
        float2 a = x[PAD(t)];
        float2 b = x[PAD(t + MH)];
        y[PAD(t)]      = make_float2(a.x + b.x, a.y + b.y);
        y[PAD(t + MH)] = make_float2(a.x - b.x, a.y - b.y);
    }
    __syncthreads();
    return y;
}

// ---------------------------------------------------------------------------
// Preprocess kernel rows: smooth (reflect pad, window 7) + soft-threshold,
// then rfft(., n=16384) -> g_kf[c][0..8192]. One block per channel.
// ---------------------------------------------------------------------------
__global__ void __launch_bounds__(NTHREADS) kern_preproc(const float* __restrict__ kern) {
    extern __shared__ float2 smem[];
    float2* sa  = smem;
    float2* sb  = smem + SBUF;
    float*  raw = (float*)sb;                 // 8192 floats fit in sb (69.6 KB)
    const int c   = blockIdx.x;
    const int tid = threadIdx.x;
    const float* kr = kern + (size_t)c * L_SIG;

    for (int i = tid; i < L_SIG; i += NTHREADS) raw[i] = kr[i];
    __syncthreads();

    // smooth + squash, pack even/odd into complex, zero-pad upper half
    for (int n = tid; n < M_FFT; n += NTHREADS) {
        if (n < MH) {
            float v[2];
            #pragma unroll
            for (int h = 0; h < 2; h++) {
                int i = 2 * n + h;
                float s = 0.f;
                #pragma unroll
                for (int j = -3; j <= 3; j++) {
                    int idx = i + j;
                    idx = (idx < 0) ? -idx : ((idx >= L_SIG) ? (2 * L_SIG - 2 - idx) : idx);
                    s += raw[idx];
                }
                s *= (1.0f / 7.0f);
                float a = fabsf(s) - KERN_LAM;
                v[h] = (a > 0.f) ? copysignf(a, s) : 0.f;
            }
            sa[PAD(n)] = make_float2(v[0], v[1]);
        } else {
            sa[PAD(n)] = make_float2(0.f, 0.f);
        }
    }
    __syncthreads();

    float2* z = fft_m(sa, sb);

    // Hermitian unpack: X[k] for k = 0..M (8193 bins) from half-size FFT
    float2* kf = g_kf + (size_t)c * (2 * MH + 1);
    for (int k = tid; k <= MH; k += NTHREADS) {
        int km = (M_FFT - k) & (M_FFT - 1);
        float2 Zk = z[PAD(k)], Zm = z[PAD(km)];
        float2 A  = make_float2(0.5f * (Zk.x + Zm.x),  0.5f * (Zk.y - Zm.y));
        float2 B  = make_float2(0.5f * (Zk.y + Zm.y), -0.5f * (Zk.x - Zm.x));
        float2 w  = g_tw2[k];
        float2 wB = cmul(w, B);
        kf[k]          = make_float2(A.x + wB.x,   A.y + wB.y);    // X[k]
        kf[2 * MH - k] = make_float2(A.x - wB.x, -(A.y - wB.y));   // X[M-k] = conj(A - wB)
    }
}

// ---------------------------------------------------------------------------
// Main: one block per (b, c) row. Load row (even/odd pack is free: the
// contiguous fp32 row IS the packed complex array), forward FFT, fused
// (unpack -> spectral multiply -> inverse-repack as conj(Z')), inverse FFT
// via conj trick, write first L samples.
// ---------------------------------------------------------------------------
__global__ void __launch_bounds__(NTHREADS) fftconv_main(const float* __restrict__ x,
                                                         float* __restrict__ out) {
    extern __shared__ float2 smem[];
    float2* sa = smem;
    float2* sb = smem + SBUF;
    const int row = blockIdx.x;
    const int c   = row & (NCH - 1);
    const int tid = threadIdx.x;
    const float2* xr   = (const float2*)(x   + (size_t)row * L_SIG);
    float2*       outr = (float2*)      (out + (size_t)row * L_SIG);

    for (int i = tid; i < MH; i += NTHREADS)          sa[PAD(i)] = xr[i];
    for (int i = MH + tid; i < M_FFT; i += NTHREADS)  sa[PAD(i)] = make_float2(0.f, 0.f);
    __syncthreads();

    float2* z  = fft_m(sa, sb);
    float2* zo = (z == sa) ? sb : sa;   // free scratch buffer

    // Fused: unpack X[k], multiply by Kf, repack conj(Z'[k]) for inverse FFT
    const float2* kf = g_kf + (size_t)c * (2 * MH + 1);
    for (int k = tid; k <= MH; k += NTHREADS) {
        int km = (M_FFT - k) & (M_FFT - 1);
        float2 Zk = z[PAD(k)], Zm = z[PAD(km)];
        float2 A  = make_float2(0.5f * (Zk.x + Zm.x),  0.5f * (Zk.y - Zm.y));
        float2 B  = make_float2(0.5f * (Zk.y + Zm.y), -0.5f * (Zk.x - Zm.x));
        float2 w  = g_tw2[k];
        float2 wB = cmul(w, B);
        float2 Xk = make_float2(A.x + wB.x,   A.y + wB.y);
        float2 Xm = make_float2(A.x - wB.x, -(A.y - wB.y));
        float2 Yk = cmul(Xk, kf[k]);
        float2 Ym = cmul(Xm, kf[2 * MH - k]);
        // inverse combine: A' = (Yk + conj Ym)/2 ; B' = conj(w) * (Yk - conj Ym)/2
        float2 Ap = make_float2(0.5f * (Yk.x + Ym.x), 0.5f * (Yk.y - Ym.y));
        float2 D  = make_float2(0.5f * (Yk.x - Ym.x), 0.5f * (Yk.y + Ym.y));
        float2 Bp = cmul(make_float2(w.x, -w.y), D);
        // store conj(Z'[k]) ; Z'[k] = A' + i*B'
        zo[PAD(k)] = make_float2(Ap.x - Bp.y, -(Ap.y + Bp.x));
        if (k != 0 && k != MH) {
            // conj(Z'[M-k]) ; Z'[M-k] = conj(A') + i*conj(B')
            zo[PAD(M_FFT - k)] = make_float2(Ap.x + Bp.y, Ap.y - Bp.x);
        }
    }
    __syncthreads();

    // inverse: IFFT(Z') = conj(FFT(conj(Z'))) / M ; emit first L real samples
    float2* zz = fft_m(zo, z);
    const float inv = 1.0f / (float)M_FFT;
    for (int n = tid; n < MH; n += NTHREADS) {
        float2 v = zz[PAD(n)];
        outr[n] = make_float2(v.x * inv, -v.y * inv);
    }
}

extern "C" void kernel_launch(void* const* d_in, const int* in_sizes, int n_in,
                              void* d_out, int out_size) {
    const float* x    = (const float*)d_in[0];
    const float* kern = (const float*)d_in[1];
    if (n_in >= 2 && in_sizes[0] < in_sizes[1]) {  // defensive: x is the big one
        const float* t = x; x = kern; kern = t;
    }
    float* out = (float*)d_out;

    const size_t smem = 2 * SBUF * sizeof(float2);  // 139,264 B ping-pong
    cudaFuncSetAttribute(kern_preproc, cudaFuncAttributeMaxDynamicSharedMemorySize, (int)smem);
    cudaFuncSetAttribute(fftconv_main, cudaFuncAttributeMaxDynamicSharedMemorySize, (int)smem);

    twiddle_init<<<M_FFT / NTHREADS, NTHREADS>>>();
    kern_preproc<<<NCH, NTHREADS, smem>>>(kern);
    fftconv_main<<<NROWS, NTHREADS, smem>>>(x, out);
}

// round 5
// speedup vs baseline: 1.7084x; 1.7084x over previous
#include <cuda_runtime.h>

// =============================================================================
// FFT convolution: out = irfft( rfft(x, 2L) * rfft(squash(smooth(kern)), 2L) )[:L]
// L = 8192, N = 2L = 16384 real FFT == M = 8192 complex FFT on even/odd packing.
// Complex FFT: 3 in-place radix-16 Stockham stages; both trivial radix-2 stages
// (s = 4096) are FUSED into the adjacent pointwise / store phases.
// Single 69.6 KB padded smem buffer -> 2 blocks/SM. One block per (b,c) row.
// =============================================================================

#define L_SIG    8192
#define M_FFT    8192      // complex FFT size (= N/2)
#define MH       4096      // M/2
#define MQ       2048      // M/4
#define NCH      256
#define NROWS    2048      // 8 * 256
#define NTHREADS 512
#define KERN_LAM 0.003f

#define PAD(i)   ((i) + ((i) >> 4))      // conflict-free smem addressing
#define SBUF     8704                     // covers PAD(8191) = 8702

// Kernel spectrum: 256 rows x 8193 complex bins (rfft of length-16384 signal)
__device__ float2 g_kf[NCH * (2 * MH + 1)];
// Twiddle tables (filled each launch; deterministic)
__device__ float2 g_tw [NTHREADS];  // exp(-2*pi*i * r / M), r in [0, 512)
__device__ float2 g_tw2[MH + 1];    // exp(-pi*i  * k / M), k in [0, 4096]

__device__ __forceinline__ float2 cmul(float2 a, float2 b) {
    return make_float2(fmaf(a.x, b.x, -a.y * b.y), fmaf(a.x, b.y, a.y * b.x));
}

__global__ void twiddle_init() {
    int i = blockIdx.x * blockDim.x + threadIdx.x;
    if (i < NTHREADS) {
        float s, c;
        sincospif(-2.0f * (float)i / (float)M_FFT, &s, &c);
        g_tw[i] = make_float2(c, s);
    }
    if (i <= MH) {
        float s, c;
        sincospif(-1.0f * (float)i / (float)M_FFT, &s, &c);
        g_tw2[i] = make_float2(c, s);
    }
}

// ---------------------------------------------------------------------------
// 4-point DFT (forward), W4 = -i.
// ---------------------------------------------------------------------------
__device__ __forceinline__ void dft4(float2 a, float2 b, float2 c, float2 d,
                                     float2& o0, float2& o1, float2& o2, float2& o3) {
    float2 apc = make_float2(a.x + c.x, a.y + c.y);
    float2 amc = make_float2(a.x - c.x, a.y - c.y);
    float2 bpd = make_float2(b.x + d.x, b.y + d.y);
    float2 bmd = make_float2(b.x - d.x, b.y - d.y);
    o0 = make_float2(apc.x + bpd.x, apc.y + bpd.y);
    o1 = make_float2(amc.x + bmd.y, amc.y - bmd.x);   // amc - i*bmd
    o2 = make_float2(apc.x - bpd.x, apc.y - bpd.y);
    o3 = make_float2(amc.x - bmd.y, amc.y + bmd.x);   // amc + i*bmd
}

// ---------------------------------------------------------------------------
// In-register 16-point forward DFT (two radix-4 layers + W16 twiddles).
// ---------------------------------------------------------------------------
__device__ __forceinline__ void dft16(float2* v) {
    const float2 W1 = make_float2( 0.9238795325112867f, -0.3826834323650898f);
    const float2 W2 = make_float2( 0.7071067811865476f, -0.7071067811865476f);
    const float2 W3 = make_float2( 0.3826834323650898f, -0.9238795325112867f);
    const float2 W6 = make_float2(-0.7071067811865476f, -0.7071067811865476f);
    const float2 W9 = make_float2(-0.9238795325112867f,  0.3826834323650898f);
    float2 A[4][4];
    #pragma unroll
    for (int n1 = 0; n1 < 4; n1++)
        dft4(v[n1], v[n1 + 4], v[n1 + 8], v[n1 + 12],
             A[n1][0], A[n1][1], A[n1][2], A[n1][3]);
    A[1][1] = cmul(A[1][1], W1);
    A[1][2] = cmul(A[1][2], W2);
    A[1][3] = cmul(A[1][3], W3);
    A[2][1] = cmul(A[2][1], W2);
    A[2][2] = make_float2(A[2][2].y, -A[2][2].x);     // * W16^4 = -i
    A[2][3] = cmul(A[2][3], W6);
    A[3][1] = cmul(A[3][1], W3);
    A[3][2] = cmul(A[3][2], W6);
    A[3][3] = cmul(A[3][3], W9);
    #pragma unroll
    for (int k1 = 0; k1 < 4; k1++)
        dft4(A[0][k1], A[1][k1], A[2][k1], A[3][k1],
             v[k1], v[k1 + 4], v[k1 + 8], v[k1 + 12]);
}

// ---------------------------------------------------------------------------
// IN-PLACE: 3 radix-16 Stockham stages (s = 1, 16, 256). Result is the
// PRE-final-radix-2 state: full FFT bin z[t] = x[t] + x[t+MH],
// z[t+MH] = x[t] - x[t+MH]. The trivial radix-2 is fused into the callers.
// Caller must __syncthreads() after writing the input. Ends with a barrier.
// ---------------------------------------------------------------------------
__device__ __forceinline__ void fft3(float2* x) {
    const int tid = threadIdx.x;
    int s = 1;
    #pragma unroll
    for (int st = 0; st < 3; st++) {
        const int q = tid & (s - 1);
        const int r = tid - q;                 // = p * s  (< 512 always)
        float2 v[16];
        #pragma unroll
        for (int i = 0; i < 16; i++) v[i] = x[PAD(tid + i * NTHREADS)];
        dft16(v);
        // twiddle powers W^{j*r} via shallow product tree
        float2 w1 = g_tw[r];
        float2 w2 = cmul(w1, w1);
        float2 w3 = cmul(w2, w1);
        float2 w4 = cmul(w2, w2);
        float2 w5 = cmul(w4, w1);
        float2 w6 = cmul(w4, w2);
        float2 w7 = cmul(w4, w3);
        float2 w8 = cmul(w4, w4);
        v[1]  = cmul(v[1],  w1);
        v[2]  = cmul(v[2],  w2);
        v[3]  = cmul(v[3],  w3);
        v[4]  = cmul(v[4],  w4);
        v[5]  = cmul(v[5],  w5);
        v[6]  = cmul(v[6],  w6);
        v[7]  = cmul(v[7],  w7);
        v[8]  = cmul(v[8],  w8);
        v[9]  = cmul(cmul(v[9],  w1), w8);
        v[10] = cmul(cmul(v[10], w2), w8);
        v[11] = cmul(cmul(v[11], w3), w8);
        v[12] = cmul(cmul(v[12], w4), w8);
        v[13] = cmul(cmul(v[13], w5), w8);
        v[14] = cmul(cmul(v[14], w6), w8);
        v[15] = cmul(cmul(v[15], w7), w8);
        __syncthreads();                       // all loads done before any store
        const int o = 16 * tid - 15 * q;
        #pragma unroll
        for (int j = 0; j < 16; j++) x[PAD(o + j * s)] = v[j];
        __syncthreads();
        s <<= 4;
    }
}

// Hermitian unpack for bin k: given z[k], z[M-k], w = e^{-pi i k / M}:
// X[k] = A + wB,  X[M-k] = conj(A - wB)
__device__ __forceinline__ void herm_unpack(float2 Zk, float2 Zm, float2 w,
                                            float2& Xk, float2& Xm) {
    float2 A  = make_float2(0.5f * (Zk.x + Zm.x),  0.5f * (Zk.y - Zm.y));
    float2 B  = make_float2(0.5f * (Zk.y + Zm.y), -0.5f * (Zk.x - Zm.x));
    float2 wB = cmul(w, B);
    Xk = make_float2(A.x + wB.x,   A.y + wB.y);
    Xm = make_float2(A.x - wB.x, -(A.y - wB.y));
}

// Inverse repack for bin k: given Y[k], Y[M-k], w: produce conj(Z'[k]) and
// conj(Z'[M-k]) for the conj-trick inverse FFT.
__device__ __forceinline__ void inv_repack(float2 Yk, float2 Ym, float2 w,
                                           float2& ok, float2& om) {
    float2 Ap = make_float2(0.5f * (Yk.x + Ym.x), 0.5f * (Yk.y - Ym.y));
    float2 D  = make_float2(0.5f * (Yk.x - Ym.x), 0.5f * (Yk.y + Ym.y));
    float2 Bp = cmul(make_float2(w.x, -w.y), D);
    ok = make_float2(Ap.x - Bp.y, -(Ap.y + Bp.x));
    om = make_float2(Ap.x + Bp.y,   Ap.y - Bp.x);
}

// ---------------------------------------------------------------------------
// Preprocess kernel rows: smooth (reflect, window 7) + soft-threshold, then
// rfft(., 16384) -> g_kf[c][0..8192]. Final radix-2 fused into the unpack.
// ---------------------------------------------------------------------------
__global__ void __launch_bounds__(NTHREADS) kern_preproc(const float* __restrict__ kern) {
    extern __shared__ float2 smem[];
    float2* sa  = smem;
    float*  raw = (float*)(smem + SBUF);
    const int c   = blockIdx.x;
    const int tid = threadIdx.x;
    const float* kr = kern + (size_t)c * L_SIG;

    for (int i = tid; i < L_SIG; i += NTHREADS) raw[i] = kr[i];
    __syncthreads();

    for (int n = tid; n < M_FFT; n += NTHREADS) {
        if (n < MH) {
            float v[2];
            #pragma unroll
            for (int h = 0; h < 2; h++) {
                int i = 2 * n + h;
                float s = 0.f;
                #pragma unroll
                for (int j = -3; j <= 3; j++) {
                    int idx = i + j;
                    idx = (idx < 0) ? -idx : ((idx >= L_SIG) ? (2 * L_SIG - 2 - idx) : idx);
                    s += raw[idx];
                }
                s *= (1.0f / 7.0f);
                float a = fabsf(s) - KERN_LAM;
                v[h] = (a > 0.f) ? copysignf(a, s) : 0.f;
            }
            sa[PAD(n)] = make_float2(v[0], v[1]);
        } else {
            sa[PAD(n)] = make_float2(0.f, 0.f);
        }
    }
    __syncthreads();

    fft3(sa);   // sa = pre-radix-2 state

    // Fused radix-2 + Hermitian unpack, bin-pairs (k, MH-k). Writes to gmem.
    float2* kf = g_kf + (size_t)c * (2 * MH + 1);
    #pragma unroll
    for (int j = 0; j < 4; j++) {
        int k = tid + j * NTHREADS;             // k in [0, MQ)
        if (k == 0) continue;
        float2 a = sa[PAD(k)],      b = sa[PAD(k + MH)];
        float2 cc = sa[PAD(MH - k)], d = sa[PAD(M_FFT - k)];
        float2 zk  = make_float2(a.x + b.x, a.y + b.y);    // z[k]
        float2 zmk = make_float2(cc.x - d.x, cc.y - d.y);  // z[M-k]
        float2 zj  = make_float2(cc.x + d.x, cc.y + d.y);  // z[MH-k]
        float2 zmj = make_float2(a.x - b.x, a.y - b.y);    // z[MH+k]
        float2 Xk, Xm;
        herm_unpack(zk, zmk, g_tw2[k], Xk, Xm);
        kf[k] = Xk;  kf[M_FFT - k] = Xm;
        herm_unpack(zj, zmj, g_tw2[MH - k], Xk, Xm);
        kf[MH - k] = Xk;  kf[MH + k] = Xm;
    }
    if (tid == 0) {
        float2 a = sa[PAD(0)], b = sa[PAD(MH)];
        float2 z0  = make_float2(a.x + b.x, a.y + b.y);    // z[0]
        float2 zm  = make_float2(a.x - b.x, a.y - b.y);    // z[MH]
        float2 Xk, Xm;
        herm_unpack(z0, z0, make_float2(1.f, 0.f), Xk, Xm);
        kf[0] = Xk;  kf[M_FFT] = Xm;
        herm_unpack(zm, zm, g_tw2[MH], Xk, Xm);
        kf[MH] = Xk;
        float2 a2 = sa[PAD(MQ)], b2 = sa[PAD(MQ + MH)];
        float2 zq  = make_float2(a2.x + b2.x, a2.y + b2.y);
        float2 zqm = make_float2(a2.x - b2.x, a2.y - b2.y);
        herm_unpack(zq, zqm, g_tw2[MQ], Xk, Xm);
        kf[MQ] = Xk;  kf[M_FFT - MQ] = Xm;
    }
}

// ---------------------------------------------------------------------------
// Main: one block per (b, c) row. Forward fft3, fused (radix-2 + unpack +
// spectral multiply + inverse repack) on thread-private 4-point groups,
// inverse fft3 via conj trick, fused (radix-2 + conj + scale + store).
// ---------------------------------------------------------------------------
__global__ void __launch_bounds__(NTHREADS, 2) fftconv_main(const float* __restrict__ x,
                                                            float* __restrict__ out) {
    extern __shared__ float2 smem[];
    const int row = blockIdx.x;
    const int c   = row & (NCH - 1);
    const int tid = threadIdx.x;
    const float4* xr4 = (const float4*)(x + (size_t)row * L_SIG);
    float4*       or4 = (float4*)(out + (size_t)row * L_SIG);

    for (int i = tid; i < MH / 2; i += NTHREADS) {
        float4 v = xr4[i];
        smem[PAD(2 * i)]     = make_float2(v.x, v.y);
        smem[PAD(2 * i + 1)] = make_float2(v.z, v.w);
    }
    for (int i = MH + tid; i < M_FFT; i += NTHREADS)
        smem[PAD(i)] = make_float2(0.f, 0.f);
    __syncthreads();

    fft3(smem);   // smem = pre-radix-2 forward state

    // Fused pointwise on bin-pairs (k, MH-k): each group of 4 smem slots
    // {k, k+MH, MH-k, M-k} is read AND written by exactly one thread.
    const float2* kf = g_kf + (size_t)c * (2 * MH + 1);
    #pragma unroll
    for (int j = 0; j < 4; j++) {
        int k = tid + j * NTHREADS;             // k in [0, MQ)
        if (k == 0) continue;
        float2 a = smem[PAD(k)],       b = smem[PAD(k + MH)];
        float2 cc = smem[PAD(MH - k)], d = smem[PAD(M_FFT - k)];
        float2 zk  = make_float2(a.x + b.x, a.y + b.y);
        float2 zmk = make_float2(cc.x - d.x, cc.y - d.y);
        float2 zj  = make_float2(cc.x + d.x, cc.y + d.y);
        float2 zmj = make_float2(a.x - b.x, a.y - b.y);
        float2 Xk, Xm, ok, om;
        float2 w = g_tw2[k];
        herm_unpack(zk, zmk, w, Xk, Xm);
        inv_repack(cmul(Xk, kf[k]), cmul(Xm, kf[M_FFT - k]), w, ok, om);
        smem[PAD(k)] = ok;  smem[PAD(M_FFT - k)] = om;
        float2 wj = g_tw2[MH - k];
        herm_unpack(zj, zmj, wj, Xk, Xm);
        inv_repack(cmul(Xk, kf[MH - k]), cmul(Xm, kf[MH + k]), wj, ok, om);
        smem[PAD(MH - k)] = ok;  smem[PAD(MH + k)] = om;
    }
    if (tid == 0) {
        float2 a = smem[PAD(0)], b = smem[PAD(MH)];
        float2 z0 = make_float2(a.x + b.x, a.y + b.y);
        float2 zm = make_float2(a.x - b.x, a.y - b.y);
        float2 Xk, Xm, ok, om;
        herm_unpack(z0, z0, make_float2(1.f, 0.f), Xk, Xm);
        inv_repack(cmul(Xk, kf[0]), cmul(Xm, kf[M_FFT]), make_float2(1.f, 0.f), ok, om);
        smem[PAD(0)] = ok;
        float2 wh = g_tw2[MH];
        herm_unpack(zm, zm, wh, Xk, Xm);
        inv_repack(cmul(Xk, kf[MH]), cmul(Xm, kf[MH]), wh, ok, om);
        smem[PAD(MH)] = ok;
        float2 a2 = smem[PAD(MQ)], b2 = smem[PAD(MQ + MH)];
        float2 zq  = make_float2(a2.x + b2.x, a2.y + b2.y);
        float2 zqm = make_float2(a2.x - b2.x, a2.y - b2.y);
        float2 wq = g_tw2[MQ];
        herm_unpack(zq, zqm, wq, Xk, Xm);
        inv_repack(cmul(Xk, kf[MQ]), cmul(Xm, kf[M_FFT - MQ]), wq, ok, om);
        smem[PAD(MQ)] = ok;  smem[PAD(MQ + MH)] = om;
    }
    __syncthreads();

    fft3(smem);   // inverse (conj trick): smem = pre-radix-2 inverse state

    // Fused final radix-2 + conj + scale + store: only lower half needed.
    // zz[n] = u[n] + u[n+MH]; out[n] = conj(zz[n]) / M.
    const float inv = 1.0f / (float)M_FFT;
    for (int i = tid; i < MH / 2; i += NTHREADS) {
        float2 a  = smem[PAD(2 * i)];
        float2 b  = smem[PAD(2 * i + 1)];
        float2 a2 = smem[PAD(2 * i + MH)];
        float2 b2 = smem[PAD(2 * i + 1 + MH)];
        or4[i] = make_float4((a.x + a2.x) * inv, -(a.y + a2.y) * inv,
                             (b.x + b2.x) * inv, -(b.y + b2.y) * inv);
    }
}

extern "C" void kernel_launch(void* const* d_in, const int* in_sizes, int n_in,
                              void* d_out, int out_size) {
    const float* x    = (const float*)d_in[0];
    const float* kern = (const float*)d_in[1];
    if (n_in >= 2 && in_sizes[0] < in_sizes[1]) {  // defensive: x is the big one
        const float* t = x; x = kern; kern = t;
    }
    float* out = (float*)d_out;

    const size_t smem_main = SBUF * sizeof(float2);                 // 69,632 B
    const size_t smem_prep = SBUF * sizeof(float2) + L_SIG * 4;     // +32 KB raw
    cudaFuncSetAttribute(kern_preproc, cudaFuncAttributeMaxDynamicSharedMemorySize, (int)smem_prep);
    cudaFuncSetAttribute(fftconv_main, cudaFuncAttributeMaxDynamicSharedMemorySize, (int)smem_main);

    twiddle_init<<<9, NTHREADS>>>();                 // 4608 threads >= 4097
    kern_preproc<<<NCH, NTHREADS, smem_prep>>>(kern);
    fftconv_main<<<NROWS, NTHREADS, smem_main>>>(x, out);
}

// round 6
// speedup vs baseline: 1.9268x; 1.1278x over previous
#include <cuda_runtime.h>

// =============================================================================
// FFT convolution: out = irfft( rfft(x, 2L) * rfft(squash(smooth(kern)), 2L) )[:L]
// L = 8192, N = 2L = 16384 real FFT == M = 8192 complex FFT on even/odd packing.
// 3 in-place radix-16 Stockham stages; trivial radix-2 stages fused into
// pointwise/store; forward stage 0 fused with the gmem load (upper half = 0).
// Single 69.6 KB padded smem buffer -> 2 blocks/SM. One block per (b,c) row.
// =============================================================================

#define L_SIG    8192
#define M_FFT    8192      // complex FFT size (= N/2)
#define MH       4096      // M/2
#define MQ       2048      // M/4
#define NCH      256
#define NROWS    2048      // 8 * 256
#define NTHREADS 512
#define KERN_LAM 0.003f

#define PAD(i)   ((i) + ((i) >> 4))      // conflict-free smem addressing
#define SBUF     8704                     // covers PAD(8191) = 8702

// Kernel spectrum: 256 rows x 8193 complex bins (rfft of length-16384 signal)
__device__ float2 g_kf[NCH * (2 * MH + 1)];
// Twiddle tables: filled cooperatively by kern_preproc, read by fftconv_main.
__device__ float2 g_tw [NTHREADS];  // exp(-2*pi*i * r / M), r in [0, 512)
__device__ float2 g_tw2[MH + 1];    // exp(-pi*i  * k / M), k in [0, 4096]

__device__ __forceinline__ float2 cmul(float2 a, float2 b) {
    return make_float2(fmaf(a.x, b.x, -a.y * b.y), fmaf(a.x, b.y, a.y * b.x));
}

// ---------------------------------------------------------------------------
// 4-point DFT (forward), W4 = -i.
// ---------------------------------------------------------------------------
__device__ __forceinline__ void dft4(float2 a, float2 b, float2 c, float2 d,
                                     float2& o0, float2& o1, float2& o2, float2& o3) {
    float2 apc = make_float2(a.x + c.x, a.y + c.y);
    float2 amc = make_float2(a.x - c.x, a.y - c.y);
    float2 bpd = make_float2(b.x + d.x, b.y + d.y);
    float2 bmd = make_float2(b.x - d.x, b.y - d.y);
    o0 = make_float2(apc.x + bpd.x, apc.y + bpd.y);
    o1 = make_float2(amc.x + bmd.y, amc.y - bmd.x);   // amc - i*bmd
    o2 = make_float2(apc.x - bpd.x, apc.y - bpd.y);
    o3 = make_float2(amc.x - bmd.y, amc.y + bmd.x);   // amc + i*bmd
}

// Second layer of the 16-point DFT (shared by dft16 / dft16h).
__device__ __forceinline__ void dft16_layer2(float2 A[4][4], float2* v) {
    const float2 W1 = make_float2( 0.9238795325112867f, -0.3826834323650898f);
    const float2 W2 = make_float2( 0.7071067811865476f, -0.7071067811865476f);
    const float2 W3 = make_float2( 0.3826834323650898f, -0.9238795325112867f);
    const float2 W6 = make_float2(-0.7071067811865476f, -0.7071067811865476f);
    const float2 W9 = make_float2(-0.9238795325112867f,  0.3826834323650898f);
    A[1][1] = cmul(A[1][1], W1);
    A[1][2] = cmul(A[1][2], W2);
    A[1][3] = cmul(A[1][3], W3);
    A[2][1] = cmul(A[2][1], W2);
    A[2][2] = make_float2(A[2][2].y, -A[2][2].x);     // * W16^4 = -i
    A[2][3] = cmul(A[2][3], W6);
    A[3][1] = cmul(A[3][1], W3);
    A[3][2] = cmul(A[3][2], W6);
    A[3][3] = cmul(A[3][3], W9);
    #pragma unroll
    for (int k1 = 0; k1 < 4; k1++)
        dft4(A[0][k1], A[1][k1], A[2][k1], A[3][k1],
             v[k1], v[k1 + 4], v[k1 + 8], v[k1 + 12]);
}

// Full in-register 16-point forward DFT.
__device__ __forceinline__ void dft16(float2* v) {
    float2 A[4][4];
    #pragma unroll
    for (int n1 = 0; n1 < 4; n1++)
        dft4(v[n1], v[n1 + 4], v[n1 + 8], v[n1 + 12],
             A[n1][0], A[n1][1], A[n1][2], A[n1][3]);
    dft16_layer2(A, v);
}

// 16-point forward DFT with inputs v[8..15] == 0 (zero-padded upper half).
// First-layer dft4(a, b, 0, 0) = {a+b, a-ib, a-b, a+ib}.
__device__ __forceinline__ void dft16h(float2* v) {
    float2 A[4][4];
    #pragma unroll
    for (int n1 = 0; n1 < 4; n1++) {
        float2 a = v[n1], b = v[n1 + 4];
        A[n1][0] = make_float2(a.x + b.x, a.y + b.y);
        A[n1][1] = make_float2(a.x + b.y, a.y - b.x);   // a - i*b
        A[n1][2] = make_float2(a.x - b.x, a.y - b.y);
        A[n1][3] = make_float2(a.x - b.y, a.y + b.x);   // a + i*b
    }
    dft16_layer2(A, v);
}

// Apply stage twiddles W_M^{j*r} to v[1..15] via a shallow product tree.
__device__ __forceinline__ void twiddle16(float2* v, float2 w1) {
    float2 w2 = cmul(w1, w1);
    float2 w3 = cmul(w2, w1);
    float2 w4 = cmul(w2, w2);
    float2 w5 = cmul(w4, w1);
    float2 w6 = cmul(w4, w2);
    float2 w7 = cmul(w4, w3);
    float2 w8 = cmul(w4, w4);
    v[1]  = cmul(v[1],  w1);
    v[2]  = cmul(v[2],  w2);
    v[3]  = cmul(v[3],  w3);
    v[4]  = cmul(v[4],  w4);
    v[5]  = cmul(v[5],  w5);
    v[6]  = cmul(v[6],  w6);
    v[7]  = cmul(v[7],  w7);
    v[8]  = cmul(v[8],  w8);
    v[9]  = cmul(cmul(v[9],  w1), w8);
    v[10] = cmul(cmul(v[10], w2), w8);
    v[11] = cmul(cmul(v[11], w3), w8);
    v[12] = cmul(cmul(v[12], w4), w8);
    v[13] = cmul(cmul(v[13], w5), w8);
    v[14] = cmul(cmul(v[14], w6), w8);
    v[15] = cmul(cmul(v[15], w7), w8);
}

// Scatter the 16 results of one Stockham butterfly: x[o + j*s] = v[j].
__device__ __forceinline__ void store16(float2* x, const float2* v, int tid, int s) {
    const int q = tid & (s - 1);
    const int o = 16 * tid - 15 * q;
    #pragma unroll
    for (int j = 0; j < 16; j++) x[PAD(o + j * s)] = v[j];
}

// One full in-place Stockham stage (load -> dft16 -> twiddle -> store).
// w1 = g_tw-style base twiddle for r = tid - (tid & (s-1)).
__device__ __forceinline__ void fft_stage(float2* x, int tid, int s, float2 w1) {
    float2 v[16];
    #pragma unroll
    for (int i = 0; i < 16; i++) v[i] = x[PAD(tid + i * NTHREADS)];
    dft16(v);
    twiddle16(v, w1);
    __syncthreads();                       // all loads done before any store
    store16(x, v, tid, s);
    __syncthreads();
}

// Hermitian unpack for bin k: given z[k], z[M-k], w = e^{-pi i k / M}:
// X[k] = A + wB,  X[M-k] = conj(A - wB)
__device__ __forceinline__ void herm_unpack(float2 Zk, float2 Zm, float2 w,
                                            float2& Xk, float2& Xm) {
    float2 A  = make_float2(0.5f * (Zk.x + Zm.x),  0.5f * (Zk.y - Zm.y));
    float2 B  = make_float2(0.5f * (Zk.y + Zm.y), -0.5f * (Zk.x - Zm.x));
    float2 wB = cmul(w, B);
    Xk = make_float2(A.x + wB.x,   A.y + wB.y);
    Xm = make_float2(A.x - wB.x, -(A.y - wB.y));
}

// Inverse repack: given Y[k], Y[M-k], w: produce conj(Z'[k]), conj(Z'[M-k]).
__device__ __forceinline__ void inv_repack(float2 Yk, float2 Ym, float2 w,
                                           float2& ok, float2& om) {
    float2 Ap = make_float2(0.5f * (Yk.x + Ym.x), 0.5f * (Yk.y - Ym.y));
    float2 D  = make_float2(0.5f * (Yk.x - Ym.x), 0.5f * (Yk.y + Ym.y));
    float2 Bp = cmul(make_float2(w.x, -w.y), D);
    ok = make_float2(Ap.x - Bp.y, -(Ap.y + Bp.x));
    om = make_float2(Ap.x + Bp.y,   Ap.y - Bp.x);
}

__device__ __forceinline__ float2 tw_main(int r) {   // exp(-2*pi*i*r/M)
    float s, c;
    sincospif(-2.0f * (float)r / (float)M_FFT, &s, &c);
    return make_float2(c, s);
}
__device__ __forceinline__ float2 tw_half(int k) {   // exp(-pi*i*k/M)
    float s, c;
    sincospif(-1.0f * (float)k / (float)M_FFT, &s, &c);
    return make_float2(c, s);
}

// ---------------------------------------------------------------------------
// Preprocess kernel rows: smooth (reflect, window 7) + soft-threshold fused
// into forward stage 0, then stages s=16,256; fused radix-2 + Hermitian
// unpack -> g_kf. Also cooperatively fills g_tw / g_tw2 for fftconv_main.
// Twiddles here are computed inline (tables not yet valid). One block/channel.
// ---------------------------------------------------------------------------
__global__ void __launch_bounds__(NTHREADS) kern_preproc(const float* __restrict__ kern) {
    extern __shared__ float2 smem[];
    float2* sa  = smem;
    float*  raw = (float*)(smem + SBUF);
    const int c   = blockIdx.x;
    const int tid = threadIdx.x;
    const float* kr = kern + (size_t)c * L_SIG;

    // fill the twiddle tables for fftconv_main (grid-strided over 256 blocks)
    {
        int gid = blockIdx.x * NTHREADS + tid;
        if (gid < NTHREADS) g_tw[gid] = tw_main(gid);
        if (gid <= MH)      g_tw2[gid] = tw_half(gid);
    }

    for (int i = tid; i < L_SIG; i += NTHREADS) raw[i] = kr[i];
    __syncthreads();

    // stage 0 fused with smooth + squash (upper half of input is zero)
    {
        float2 v[16];
        #pragma unroll
        for (int i = 0; i < 8; i++) {
            int n = tid + i * NTHREADS;        // n < 4096
            float vv[2];
            #pragma unroll
            for (int h = 0; h < 2; h++) {
                int p = 2 * n + h;
                float s = 0.f;
                #pragma unroll
                for (int j = -3; j <= 3; j++) {
                    int idx = p + j;
                    idx = (idx < 0) ? -idx : ((idx >= L_SIG) ? (2 * L_SIG - 2 - idx) : idx);
                    s += raw[idx];
                }
                s *= (1.0f / 7.0f);
                float a = fabsf(s) - KERN_LAM;
                vv[h] = (a > 0.f) ? copysignf(a, s) : 0.f;
            }
            v[i] = make_float2(vv[0], vv[1]);
        }
        dft16h(v);
        twiddle16(v, tw_main(tid));            // s=1: r = tid
        store16(sa, v, tid, 1);
        __syncthreads();
    }
    fft_stage(sa, tid, 16,  tw_main(tid & ~15));
    fft_stage(sa, tid, 256, tw_main(tid & ~255));

    // Fused radix-2 + Hermitian unpack, bin-pairs (k, MH-k). Writes to gmem.
    float2* kf = g_kf + (size_t)c * (2 * MH + 1);
    #pragma unroll
    for (int j = 0; j < 4; j++) {
        int k = tid + j * NTHREADS;             // k in [0, MQ)
        if (k == 0) continue;
        float2 a = sa[PAD(k)],      b = sa[PAD(k + MH)];
        float2 cc = sa[PAD(MH - k)], d = sa[PAD(M_FFT - k)];
        float2 zk  = make_float2(a.x + b.x, a.y + b.y);    // z[k]
        float2 zmk = make_float2(cc.x - d.x, cc.y - d.y);  // z[M-k]
        float2 zj  = make_float2(cc.x + d.x, cc.y + d.y);  // z[MH-k]
        float2 zmj = make_float2(a.x - b.x, a.y - b.y);    // z[MH+k]
        float2 Xk, Xm;
        herm_unpack(zk, zmk, tw_half(k), Xk, Xm);
        kf[k] = Xk;  kf[M_FFT - k] = Xm;
        herm_unpack(zj, zmj, tw_half(MH - k), Xk, Xm);
        kf[MH - k] = Xk;  kf[MH + k] = Xm;
    }
    if (tid == 0) {
        float2 a = sa[PAD(0)], b = sa[PAD(MH)];
        float2 z0  = make_float2(a.x + b.x, a.y + b.y);    // z[0]
        float2 zm  = make_float2(a.x - b.x, a.y - b.y);    // z[MH]
        float2 Xk, Xm;
        herm_unpack(z0, z0, make_float2(1.f, 0.f), Xk, Xm);
        kf[0] = Xk;  kf[M_FFT] = Xm;
        herm_unpack(zm, zm, tw_half(MH), Xk, Xm);
        kf[MH] = Xk;
        float2 a2 = sa[PAD(MQ)], b2 = sa[PAD(MQ + MH)];
        float2 zq  = make_float2(a2.x + b2.x, a2.y + b2.y);
        float2 zqm = make_float2(a2.x - b2.x, a2.y - b2.y);
        herm_unpack(zq, zqm, tw_half(MQ), Xk, Xm);
        kf[MQ] = Xk;  kf[M_FFT - MQ] = Xm;
    }
}

// ---------------------------------------------------------------------------
// Main: one block per (b, c) row. Forward stage 0 fused with the gmem load
// (upper half zero -> dft16h), stages s=16,256; fused pointwise; inverse
// 3 stages via conj trick; fused radix-2 + conj + scale + store.
// ---------------------------------------------------------------------------
__global__ void __launch_bounds__(NTHREADS, 2) fftconv_main(const float* __restrict__ x,
                                                            float* __restrict__ out) {
    extern __shared__ float2 smem[];
    const int row = blockIdx.x;
    const int c   = row & (NCH - 1);
    const int tid = threadIdx.x;
    const float2* xr2 = (const float2*)(x + (size_t)row * L_SIG);
    float4*       or4 = (float4*)(out + (size_t)row * L_SIG);

    // forward stage 0 fused with gmem load (z[n>=MH] = 0)
    {
        float2 v[16];
        #pragma unroll
        for (int i = 0; i < 8; i++) v[i] = xr2[tid + i * NTHREADS];
        dft16h(v);
        twiddle16(v, g_tw[tid]);               // s=1: r = tid
        store16(smem, v, tid, 1);
        __syncthreads();
    }
    fft_stage(smem, tid, 16,  g_tw[tid & ~15]);
    fft_stage(smem, tid, 256, g_tw[tid & ~255]);

    // Fused pointwise on bin-pairs (k, MH-k): each group of 4 smem slots
    // {k, k+MH, MH-k, M-k} is read AND written by exactly one thread.
    const float2* kf = g_kf + (size_t)c * (2 * MH + 1);
    #pragma unroll
    for (int j = 0; j < 4; j++) {
        int k = tid + j * NTHREADS;             // k in [0, MQ)
        if (k == 0) continue;
        float2 a = smem[PAD(k)],       b = smem[PAD(k + MH)];
        float2 cc = smem[PAD(MH - k)], d = smem[PAD(M_FFT - k)];
        float2 zk  = make_float2(a.x + b.x, a.y + b.y);
        float2 zmk = make_float2(cc.x - d.x, cc.y - d.y);
        float2 zj  = make_float2(cc.x + d.x, cc.y + d.y);
        float2 zmj = make_float2(a.x - b.x, a.y - b.y);
        float2 Xk, Xm, ok, om;
        float2 w = g_tw2[k];
        herm_unpack(zk, zmk, w, Xk, Xm);
        inv_repack(cmul(Xk, kf[k]), cmul(Xm, kf[M_FFT - k]), w, ok, om);
        smem[PAD(k)] = ok;  smem[PAD(M_FFT - k)] = om;
        float2 wj = g_tw2[MH - k];
        herm_unpack(zj, zmj, wj, Xk, Xm);
        inv_repack(cmul(Xk, kf[MH - k]), cmul(Xm, kf[MH + k]), wj, ok, om);
        smem[PAD(MH - k)] = ok;  smem[PAD(MH + k)] = om;
    }
    if (tid == 0) {
        float2 a = smem[PAD(0)], b = smem[PAD(MH)];
        float2 z0 = make_float2(a.x + b.x, a.y + b.y);
        float2 zm = make_float2(a.x - b.x, a.y - b.y);
        float2 Xk, Xm, ok, om;
        herm_unpack(z0, z0, make_float2(1.f, 0.f), Xk, Xm);
        inv_repack(cmul(Xk, kf[0]), cmul(Xm, kf[M_FFT]), make_float2(1.f, 0.f), ok, om);
        smem[PAD(0)] = ok;
        float2 wh = g_tw2[MH];
        herm_unpack(zm, zm, wh, Xk, Xm);
        inv_repack(cmul(Xk, kf[MH]), cmul(Xm, kf[MH]), wh, ok, om);
        smem[PAD(MH)] = ok;
        float2 a2 = smem[PAD(MQ)], b2 = smem[PAD(MQ + MH)];
        float2 zq  = make_float2(a2.x + b2.x, a2.y + b2.y);
        float2 zqm = make_float2(a2.x - b2.x, a2.y - b2.y);
        float2 wq = g_tw2[MQ];
        herm_unpack(zq, zqm, wq, Xk, Xm);
        inv_repack(cmul(Xk, kf[MQ]), cmul(Xm, kf[M_FFT - MQ]), wq, ok, om);
        smem[PAD(MQ)] = ok;  smem[PAD(MQ + MH)] = om;
    }
    __syncthreads();

    // inverse FFT (conj trick): 3 full stages
    fft_stage(smem, tid, 1,   g_tw[tid]);
    fft_stage(smem, tid, 16,  g_tw[tid & ~15]);
    fft_stage(smem, tid, 256, g_tw[tid & ~255]);

    // Fused final radix-2 + conj + scale + store: only lower half needed.
    // zz[n] = u[n] + u[n+MH]; out[n] = conj(zz[n]) / M.
    const float inv = 1.0f / (float)M_FFT;
    for (int i = tid; i < MH / 2; i += NTHREADS) {
        float2 a  = smem[PAD(2 * i)];
        float2 b  = smem[PAD(2 * i + 1)];
        float2 a2 = smem[PAD(2 * i + MH)];
        float2 b2 = smem[PAD(2 * i + 1 + MH)];
        or4[i] = make_float4((a.x + a2.x) * inv, -(a.y + a2.y) * inv,
                             (b.x + b2.x) * inv, -(b.y + b2.y) * inv);
    }
}

extern "C" void kernel_launch(void* const* d_in, const int* in_sizes, int n_in,
                              void* d_out, int out_size) {
    const float* x    = (const float*)d_in[0];
    const float* kern = (const float*)d_in[1];
    if (n_in >= 2 && in_sizes[0] < in_sizes[1]) {  // defensive: x is the big one
        const float* t = x; x = kern; kern = t;
    }
    float* out = (float*)d_out;

    const size_t smem_main = SBUF * sizeof(float2);                 // 69,632 B
    const size_t smem_prep = SBUF * sizeof(float2) + L_SIG * 4;     // +32 KB raw
    cudaFuncSetAttribute(kern_preproc, cudaFuncAttributeMaxDynamicSharedMemorySize, (int)smem_prep);
    cudaFuncSetAttribute(fftconv_main, cudaFuncAttributeMaxDynamicSharedMemorySize, (int)smem_main);

    kern_preproc<<<NCH, NTHREADS, smem_prep>>>(kern);
    fftconv_main<<<NROWS, NTHREADS, smem_main>>>(x, out);
}

// round 12
// speedup vs baseline: 2.1360x; 1.1086x over previous
#include <cuda_runtime.h>

// =============================================================================
// FFT convolution: out = irfft( rfft(x, 2L) * rfft(squash(smooth(kern)), 2L) )[:L]
// L = 8192, N = 2L = 16384 real FFT == M = 8192 complex FFT on even/odd packing.
// 3 in-place radix-16 Stockham stages (f32x2 packed adds, imm-offset smem,
// stage-256 constant twiddles); trivial radix-2 stages fused into
// pointwise/store; forward stage 0 fused with the gmem load (upper half = 0).
// Single 69.6 KB padded smem buffer -> 2 blocks/SM. One block per (b,c) row.
// [R12 = measurement rerun of R7-R11: GPU unavailable; source unchanged.]
// =============================================================================

#define L_SIG    8192
#define M_FFT    8192      // complex FFT size (= N/2)
#define MH       4096      // M/2
#define MQ       2048      // M/4
#define NCH      256
#define NROWS    2048      // 8 * 256
#define NTHREADS 512
#define KERN_LAM 0.003f

#define PAD(i)   ((i) + ((i) >> 4))      // conflict-free smem addressing
#define SBUF     8704                     // covers PAD(8191) = 8702

// Kernel spectrum: 256 rows x 8193 complex bins (rfft of length-16384 signal)
__device__ float2 g_kf[NCH * (2 * MH + 1)];
// Twiddle tables: filled cooperatively by kern_preproc, read by fftconv_main.
__device__ float2 g_tw [NTHREADS];  // exp(-2*pi*i * r / M), r in [0, 512)
__device__ float2 g_tw2[MH + 1];    // exp(-pi*i  * k / M), k in [0, 4096]

__device__ __forceinline__ float2 cmul(float2 a, float2 b) {
    return make_float2(fmaf(a.x, b.x, -a.y * b.y), fmaf(a.x, b.y, a.y * b.x));
}

// ---- packed f32x2 complex add/sub (sm_100+): 1 instruction per complex op ----
__device__ __forceinline__ float2 cadd(float2 a, float2 b) {
    unsigned long long ua, ub, ur;
    asm("mov.b64 %0, {%1, %2};" : "=l"(ua) : "f"(a.x), "f"(a.y));
    asm("mov.b64 %0, {%1, %2};" : "=l"(ub) : "f"(b.x), "f"(b.y));
    asm("add.rn.f32x2 %0, %1, %2;" : "=l"(ur) : "l"(ua), "l"(ub));
    float2 r;
    asm("mov.b64 {%0, %1}, %2;" : "=f"(r.x), "=f"(r.y) : "l"(ur));
    return r;
}
__device__ __forceinline__ float2 csub(float2 a, float2 b) {
    unsigned long long ua, ub, ur;
    asm("mov.b64 %0, {%1, %2};" : "=l"(ua) : "f"(a.x), "f"(a.y));
    asm("mov.b64 %0, {%1, %2};" : "=l"(ub) : "f"(b.x), "f"(b.y));
    asm("sub.rn.f32x2 %0, %1, %2;" : "=l"(ur) : "l"(ua), "l"(ub));
    float2 r;
    asm("mov.b64 {%0, %1}, %2;" : "=f"(r.x), "=f"(r.y) : "l"(ur));
    return r;
}

// ---------------------------------------------------------------------------
// 4-point DFT (forward), W4 = -i, using packed complex add/sub.
// ---------------------------------------------------------------------------
__device__ __forceinline__ void dft4(float2 a, float2 b, float2 c, float2 d,
                                     float2& o0, float2& o1, float2& o2, float2& o3) {
    float2 apc = cadd(a, c);
    float2 amc = csub(a, c);
    float2 bpd = cadd(b, d);
    float2 bmd = csub(b, d);
    o0 = cadd(apc, bpd);
    o2 = csub(apc, bpd);
    float2 t = make_float2(bmd.y, -bmd.x);   // -i * bmd
    o1 = cadd(amc, t);
    o3 = csub(amc, t);
}

// Second layer of the 16-point DFT (shared by dft16 / dft16h).
__device__ __forceinline__ void dft16_layer2(float2 A[4][4], float2* v) {
    const float2 W1 = make_float2( 0.9238795325112867f, -0.3826834323650898f);
    const float2 W2 = make_float2( 0.7071067811865476f, -0.7071067811865476f);
    const float2 W3 = make_float2( 0.3826834323650898f, -0.9238795325112867f);
    const float2 W6 = make_float2(-0.7071067811865476f, -0.7071067811865476f);
    const float2 W9 = make_float2(-0.9238795325112867f,  0.3826834323650898f);
    A[1][1] = cmul(A[1][1], W1);
    A[1][2] = cmul(A[1][2], W2);
    A[1][3] = cmul(A[1][3], W3);
    A[2][1] = cmul(A[2][1], W2);
    A[2][2] = make_float2(A[2][2].y, -A[2][2].x);     // * W16^4 = -i
    A[2][3] = cmul(A[2][3], W6);
    A[3][1] = cmul(A[3][1], W3);
    A[3][2] = cmul(A[3][2], W6);
    A[3][3] = cmul(A[3][3], W9);
    #pragma unroll
    for (int k1 = 0; k1 < 4; k1++)
        dft4(A[0][k1], A[1][k1], A[2][k1], A[3][k1],
             v[k1], v[k1 + 4], v[k1 + 8], v[k1 + 12]);
}

// Full in-register 16-point forward DFT.
__device__ __forceinline__ void dft16(float2* v) {
    float2 A[4][4];
    #pragma unroll
    for (int n1 = 0; n1 < 4; n1++)
        dft4(v[n1], v[n1 + 4], v[n1 + 8], v[n1 + 12],
             A[n1][0], A[n1][1], A[n1][2], A[n1][3]);
    dft16_layer2(A, v);
}

// 16-point forward DFT with inputs v[8..15] == 0 (zero-padded upper half).
// First-layer dft4(a, b, 0, 0) = {a+b, a-ib, a-b, a+ib}.
__device__ __forceinline__ void dft16h(float2* v) {
    float2 A[4][4];
    #pragma unroll
    for (int n1 = 0; n1 < 4; n1++) {
        float2 a = v[n1], b = v[n1 + 4];
        float2 t = make_float2(b.y, -b.x);   // -i * b
        A[n1][0] = cadd(a, b);
        A[n1][1] = cadd(a, t);
        A[n1][2] = csub(a, b);
        A[n1][3] = csub(a, t);
    }
    dft16_layer2(A, v);
}

// Apply stage twiddles W_M^{j*r} to v[1..15] via a shallow product tree.
__device__ __forceinline__ void twiddle16(float2* v, float2 w1) {
    float2 w2 = cmul(w1, w1);
    float2 w3 = cmul(w2, w1);
    float2 w4 = cmul(w2, w2);
    float2 w5 = cmul(w4, w1);
    float2 w6 = cmul(w4, w2);
    float2 w7 = cmul(w4, w3);
    float2 w8 = cmul(w4, w4);
    v[1]  = cmul(v[1],  w1);
    v[2]  = cmul(v[2],  w2);
    v[3]  = cmul(v[3],  w3);
    v[4]  = cmul(v[4],  w4);
    v[5]  = cmul(v[5],  w5);
    v[6]  = cmul(v[6],  w6);
    v[7]  = cmul(v[7],  w7);
    v[8]  = cmul(v[8],  w8);
    v[9]  = cmul(cmul(v[9],  w1), w8);
    v[10] = cmul(cmul(v[10], w2), w8);
    v[11] = cmul(cmul(v[11], w3), w8);
    v[12] = cmul(cmul(v[12], w4), w8);
    v[13] = cmul(cmul(v[13], w5), w8);
    v[14] = cmul(cmul(v[14], w6), w8);
    v[15] = cmul(cmul(v[15], w7), w8);
}

// Scatter the 16 results of one Stockham butterfly with immediate offsets:
// PAD(o + j*s) = PAD(o) + j*K, K = s + s/16 (s >= 16), K = 1 (s = 1). Exact.
__device__ __forceinline__ void store16(float2* x, const float2* v, int tid, int s) {
    const int q = tid & (s - 1);
    float2* xb = x + PAD(16 * tid - 15 * q);
    const int K = (s == 1) ? 1 : s + (s >> 4);
    #pragma unroll
    for (int j = 0; j < 16; j++) xb[j * K] = v[j];
}

// Gather 16 butterfly inputs: PAD(tid + i*512) = PAD(tid) + i*544. Exact.
__device__ __forceinline__ void load16(const float2* x, float2* v, int tid) {
    const float2* xb = x + PAD(tid);
    #pragma unroll
    for (int i = 0; i < 16; i++) v[i] = xb[i * 544];
}

// One full in-place Stockham stage (load -> dft16 -> twiddle -> store).
__device__ __forceinline__ void fft_stage(float2* x, int tid, int s, float2 w1) {
    float2 v[16];
    load16(x, v, tid);
    dft16(v);
    twiddle16(v, w1);
    __syncthreads();                       // all loads done before any store
    store16(x, v, tid, s);
    __syncthreads();
}

// Stage s=256 specialization: r = tid & ~255 is 0 (no twiddles) or 256
// (twiddles = W_32^j, compile-time constants). Branch is warp-uniform.
__device__ __forceinline__ void fft_stage256(float2* x, int tid) {
    float2 v[16];
    load16(x, v, tid);
    dft16(v);
    if (tid >= 256) {
        v[1]  = cmul(v[1],  make_float2( 0.9807852804032304f, -0.1950903220161283f));
        v[2]  = cmul(v[2],  make_float2( 0.9238795325112867f, -0.3826834323650898f));
        v[3]  = cmul(v[3],  make_float2( 0.8314696123025452f, -0.5555702330196022f));
        v[4]  = cmul(v[4],  make_float2( 0.7071067811865476f, -0.7071067811865476f));
        v[5]  = cmul(v[5],  make_float2( 0.5555702330196022f, -0.8314696123025452f));
        v[6]  = cmul(v[6],  make_float2( 0.3826834323650898f, -0.9238795325112867f));
        v[7]  = cmul(v[7],  make_float2( 0.1950903220161283f, -0.9807852804032304f));
        v[8]  = make_float2(v[8].y, -v[8].x);                 // * (0, -1)
        v[9]  = cmul(v[9],  make_float2(-0.1950903220161283f, -0.9807852804032304f));
        v[10] = cmul(v[10], make_float2(-0.3826834323650898f, -0.9238795325112867f));
        v[11] = cmul(v[11], make_float2(-0.5555702330196022f, -0.8314696123025452f));
        v[12] = cmul(v[12], make_float2(-0.7071067811865476f, -0.7071067811865476f));
        v[13] = cmul(v[13], make_float2(-0.8314696123025452f, -0.5555702330196022f));
        v[14] = cmul(v[14], make_float2(-0.9238795325112867f, -0.3826834323650898f));
        v[15] = cmul(v[15], make_float2(-0.9807852804032304f, -0.1950903220161283f));
    }
    __syncthreads();
    store16(x, v, tid, 256);
    __syncthreads();
}

// Hermitian unpack for bin k: given z[k], z[M-k], w = e^{-pi i k / M}:
// X[k] = A + wB,  X[M-k] = conj(A - wB)
__device__ __forceinline__ void herm_unpack(float2 Zk, float2 Zm, float2 w,
                                            float2& Xk, float2& Xm) {
    float2 A  = make_float2(0.5f * (Zk.x + Zm.x),  0.5f * (Zk.y - Zm.y));
    float2 B  = make_float2(0.5f * (Zk.y + Zm.y), -0.5f * (Zk.x - Zm.x));
    float2 wB = cmul(w, B);
    Xk = cadd(A, wB);
    Xm = csub(A, wB);  Xm.y = -Xm.y;
}

// Inverse repack: given Y[k], Y[M-k], w: produce conj(Z'[k]), conj(Z'[M-k]).
__device__ __forceinline__ void inv_repack(float2 Yk, float2 Ym, float2 w,
                                           float2& ok, float2& om) {
    float2 Ap = make_float2(0.5f * (Yk.x + Ym.x), 0.5f * (Yk.y - Ym.y));
    float2 D  = make_float2(0.5f * (Yk.x - Ym.x), 0.5f * (Yk.y + Ym.y));
    float2 Bp = cmul(make_float2(w.x, -w.y), D);
    ok = make_float2(Ap.x - Bp.y, -(Ap.y + Bp.x));
    om = make_float2(Ap.x + Bp.y,   Ap.y - Bp.x);
}

__device__ __forceinline__ float2 tw_main(int r) {   // exp(-2*pi*i*r/M)
    float s, c;
    sincospif(-2.0f * (float)r / (float)M_FFT, &s, &c);
    return make_float2(c, s);
}
__device__ __forceinline__ float2 tw_half(int k) {   // exp(-pi*i*k/M)
    float s, c;
    sincospif(-1.0f * (float)k / (float)M_FFT, &s, &c);
    return make_float2(c, s);
}

// ---------------------------------------------------------------------------
// Preprocess kernel rows: smooth (reflect, window 7) + soft-threshold fused
// into forward stage 0, then stages s=16,256; fused radix-2 + Hermitian
// unpack -> g_kf. Also cooperatively fills g_tw / g_tw2 for fftconv_main.
// ---------------------------------------------------------------------------
__global__ void __launch_bounds__(NTHREADS) kern_preproc(const float* __restrict__ kern) {
    extern __shared__ float2 smem[];
    float2* sa  = smem;
    float*  raw = (float*)(smem + SBUF);
    const int c   = blockIdx.x;
    const int tid = threadIdx.x;
    const float* kr = kern + (size_t)c * L_SIG;

    // fill the twiddle tables for fftconv_main (grid-strided over 256 blocks)
    {
        int gid = blockIdx.x * NTHREADS + tid;
        if (gid < NTHREADS) g_tw[gid] = tw_main(gid);
        if (gid <= MH)      g_tw2[gid] = tw_half(gid);
    }

    for (int i = tid; i < L_SIG; i += NTHREADS) raw[i] = kr[i];
    __syncthreads();

    // stage 0 fused with smooth + squash (upper half of input is zero)
    {
        float2 v[16];
        #pragma unroll
        for (int i = 0; i < 8; i++) {
            int n = tid + i * NTHREADS;        // n < 4096
            float vv[2];
            #pragma unroll
            for (int h = 0; h < 2; h++) {
                int p = 2 * n + h;
                float s = 0.f;
                #pragma unroll
                for (int j = -3; j <= 3; j++) {
                    int idx = p + j;
                    idx = (idx < 0) ? -idx : ((idx >= L_SIG) ? (2 * L_SIG - 2 - idx) : idx);
                    s += raw[idx];
                }
                s *= (1.0f / 7.0f);
                float a = fabsf(s) - KERN_LAM;
                vv[h] = (a > 0.f) ? copysignf(a, s) : 0.f;
            }
            v[i] = make_float2(vv[0], vv[1]);
        }
        dft16h(v);
        twiddle16(v, tw_main(tid));            // s=1: r = tid
        store16(sa, v, tid, 1);
        __syncthreads();
    }
    fft_stage(sa, tid, 16, tw_main(tid & ~15));
    fft_stage256(sa, tid);

    // Fused radix-2 + Hermitian unpack, bin-pairs (k, MH-k). Writes to gmem.
    float2* kf = g_kf + (size_t)c * (2 * MH + 1);
    #pragma unroll
    for (int j = 0; j < 4; j++) {
        int k = tid + j * NTHREADS;             // k in [0, MQ)
        if (k == 0) continue;
        float2 a = sa[PAD(k)],      b = sa[PAD(k + MH)];
        float2 cc = sa[PAD(MH - k)], d = sa[PAD(M_FFT - k)];
        float2 zk  = cadd(a, b);                           // z[k]
        float2 zmk = csub(cc, d);                          // z[M-k]
        float2 zj  = cadd(cc, d);                          // z[MH-k]
        float2 zmj = csub(a, b);                           // z[MH+k]
        float2 Xk, Xm;
        herm_unpack(zk, zmk, tw_half(k), Xk, Xm);
        kf[k] = Xk;  kf[M_FFT - k] = Xm;
        herm_unpack(zj, zmj, tw_half(MH - k), Xk, Xm);
        kf[MH - k] = Xk;  kf[MH + k] = Xm;
    }
    if (tid == 0) {
        float2 a = sa[PAD(0)], b = sa[PAD(MH)];
        float2 z0  = cadd(a, b);                           // z[0]
        float2 zm  = csub(a, b);                           // z[MH]
        float2 Xk, Xm;
        herm_unpack(z0, z0, make_float2(1.f, 0.f), Xk, Xm);
        kf[0] = Xk;  kf[M_FFT] = Xm;
        herm_unpack(zm, zm, tw_half(MH), Xk, Xm);
        kf[MH] = Xk;
        float2 a2 = sa[PAD(MQ)], b2 = sa[PAD(MQ + MH)];
        float2 zq  = cadd(a2, b2);
        float2 zqm = csub(a2, b2);
        herm_unpack(zq, zqm, tw_half(MQ), Xk, Xm);
        kf[MQ] = Xk;  kf[M_FFT - MQ] = Xm;
    }
}

// ---------------------------------------------------------------------------
// Main: one block per (b, c) row. Forward stage 0 fused with the gmem load
// (upper half zero -> dft16h), stages s=16,256; fused pointwise; inverse
// 3 stages via conj trick; fused radix-2 + conj + scale + store.
// ---------------------------------------------------------------------------
__global__ void __launch_bounds__(NTHREADS, 2) fftconv_main(const float* __restrict__ x,
                                                            float* __restrict__ out) {
    extern __shared__ float2 smem[];
    const int row = blockIdx.x;
    const int c   = row & (NCH - 1);
    const int tid = threadIdx.x;
    const float2* xr2 = (const float2*)(x + (size_t)row * L_SIG);
    float4*       or4 = (float4*)(out + (size_t)row * L_SIG);

    // forward stage 0 fused with gmem load (z[n>=MH] = 0)
    {
        float2 v[16];
        #pragma unroll
        for (int i = 0; i < 8; i++) v[i] = xr2[tid + i * NTHREADS];
        dft16h(v);
        twiddle16(v, g_tw[tid]);               // s=1: r = tid
        store16(smem, v, tid, 1);
        __syncthreads();
    }
    fft_stage(smem, tid, 16, g_tw[tid & ~15]);
    fft_stage256(smem, tid);

    // Fused pointwise on bin-pairs (k, MH-k): each group of 4 smem slots
    // {k, k+MH, MH-k, M-k} is read AND written by exactly one thread.
    const float2* kf = g_kf + (size_t)c * (2 * MH + 1);
    #pragma unroll
    for (int j = 0; j < 4; j++) {
        int k = tid + j * NTHREADS;             // k in [0, MQ)
        if (k == 0) continue;
        float2 a = smem[PAD(k)],       b = smem[PAD(k + MH)];
        float2 cc = smem[PAD(MH - k)], d = smem[PAD(M_FFT - k)];
        float2 zk  = cadd(a, b);
        float2 zmk = csub(cc, d);
        float2 zj  = cadd(cc, d);
        float2 zmj = csub(a, b);
        float2 Xk, Xm, ok, om;
        float2 w = g_tw2[k];
        herm_unpack(zk, zmk, w, Xk, Xm);
        inv_repack(cmul(Xk, kf[k]), cmul(Xm, kf[M_FFT - k]), w, ok, om);
        smem[PAD(k)] = ok;  smem[PAD(M_FFT - k)] = om;
        float2 wj = g_tw2[MH - k];
        herm_unpack(zj, zmj, wj, Xk, Xm);
        inv_repack(cmul(Xk, kf[MH - k]), cmul(Xm, kf[MH + k]), wj, ok, om);
        smem[PAD(MH - k)] = ok;  smem[PAD(MH + k)] = om;
    }
    if (tid == 0) {
        float2 a = smem[PAD(0)], b = smem[PAD(MH)];
        float2 z0 = cadd(a, b);
        float2 zm = csub(a, b);
        float2 Xk, Xm, ok, om;
        herm_unpack(z0, z0, make_float2(1.f, 0.f), Xk, Xm);
        inv_repack(cmul(Xk, kf[0]), cmul(Xm, kf[M_FFT]), make_float2(1.f, 0.f), ok, om);
        smem[PAD(0)] = ok;
        float2 wh = g_tw2[MH];
        herm_unpack(zm, zm, wh, Xk, Xm);
        inv_repack(cmul(Xk, kf[MH]), cmul(Xm, kf[MH]), wh, ok, om);
        smem[PAD(MH)] = ok;
        float2 a2 = smem[PAD(MQ)], b2 = smem[PAD(MQ + MH)];
        float2 zq  = cadd(a2, b2);
        float2 zqm = csub(a2, b2);
        float2 wq = g_tw2[MQ];
        herm_unpack(zq, zqm, wq, Xk, Xm);
        inv_repack(cmul(Xk, kf[MQ]), cmul(Xm, kf[M_FFT - MQ]), wq, ok, om);
        smem[PAD(MQ)] = ok;  smem[PAD(MQ + MH)] = om;
    }
    __syncthreads();

    // inverse FFT (conj trick): 3 full stages
    fft_stage(smem, tid, 1,  g_tw[tid]);
    fft_stage(smem, tid, 16, g_tw[tid & ~15]);
    fft_stage256(smem, tid);

    // Fused final radix-2 + conj + scale + store: only lower half needed.
    // zz[n] = u[n] + u[n+MH]; out[n] = conj(zz[n]) / M.
    const float inv = 1.0f / (float)M_FFT;
    for (int i = tid; i < MH / 2; i += NTHREADS) {
        float2 sa2 = cadd(smem[PAD(2 * i)],     smem[PAD(2 * i + MH)]);
        float2 sb2 = cadd(smem[PAD(2 * i + 1)], smem[PAD(2 * i + 1 + MH)]);
        or4[i] = make_float4(sa2.x * inv, -sa2.y * inv, sb2.x * inv, -sb2.y * inv);
    }
}

extern "C" void kernel_launch(void* const* d_in, const int* in_sizes, int n_in,
                              void* d_out, int out_size) {
    const float* x    = (const float*)d_in[0];
    const float* kern = (const float*)d_in[1];
    if (n_in >= 2 && in_sizes[0] < in_sizes[1]) {  // defensive: x is the big one
        const float* t = x; x = kern; kern = t;
    }
    float* out = (float*)d_out;

    const size_t smem_main = SBUF * sizeof(float2);                 // 69,632 B
    const size_t smem_prep = SBUF * sizeof(float2) + L_SIG * 4;     // +32 KB raw
    cudaFuncSetAttribute(kern_preproc, cudaFuncAttributeMaxDynamicSharedMemorySize, (int)smem_prep);
    cudaFuncSetAttribute(fftconv_main, cudaFuncAttributeMaxDynamicSharedMemorySize, (int)smem_main);

    kern_preproc<<<NCH, NTHREADS, smem_prep>>>(kern);
    fftconv_main<<<NROWS, NTHREADS, smem_main>>>(x, out);
}